// round 4
// baseline (speedup 1.0000x reference)
#include <cuda_runtime.h>
#include <cstdint>

// Problem constants
#define NGROUP 16
#define CPG    8            // channels per group
#define C      128          // total channels
#define HW     (512 * 512)  // pixels per plane
#define BATCH  4
#define PX_TILE 256         // pixels per CTA (two 128-px slices)
#define THREADS 256         // 8 warps; warp w handles groups (15-w) and (w)

typedef unsigned long long u64;

// Duplicated transposed weights: g_W2[k * C + co] = {w[co][k], w[co][k]} packed
__device__ u64 g_W2[C * C];

__global__ void build_w2_kernel(const float* __restrict__ w) {
    int co = blockIdx.x;   // 0..127
    int k  = threadIdx.x;  // 0..127
    float v = w[co * C + k];
    u64 r;
    unsigned u = __float_as_uint(v);
    asm("mov.b64 %0, {%1, %1};" : "=l"(r) : "r"(u));
    g_W2[k * C + co] = r;
}

// ---- packed f32x2 helpers (Blackwell) ----
__device__ __forceinline__ u64 pack2(float v) {
    u64 r;
    unsigned u = __float_as_uint(v);
    asm("mov.b64 %0, {%1, %1};" : "=l"(r) : "r"(u));
    return r;
}
__device__ __forceinline__ void fma2(u64& d, u64 a, u64 b) {
    asm("fma.rn.f32x2 %0, %1, %2, %0;" : "+l"(d) : "l"(a), "l"(b));
}
__device__ __forceinline__ u64 add2(u64 a, u64 b) {
    u64 r;
    asm("add.rn.f32x2 %0, %1, %2;" : "=l"(r) : "l"(a), "l"(b));
    return r;
}

// One output group g for this warp. Thread pixel slices:
//   slice0 = px [4*lane, 4*lane+4)        (coalesced 512B per LDG.128)
//   slice1 = px [128 + 4*lane, ... +4)
__device__ __forceinline__ void do_group(
    int g, const float* __restrict__ xlane,
    const float* __restrict__ bias, float* __restrict__ olane)
{
    const int kmax = (g + 1) * CPG;
    const int co0  = g * CPG;

    // 8 weights per k-row for this group = 4 ulonglong2, starting at u64
    // element co0 within the row (row stride = C u64 = C/2 ulonglong2).
    const ulonglong2* wrow =
        reinterpret_cast<const ulonglong2*>(g_W2 + co0);

    u64 acc[8][4];
#pragma unroll
    for (int j = 0; j < 8; ++j)
#pragma unroll
        for (int q = 0; q < 4; ++q) acc[j][q] = 0ull;

    // current-iteration operands (prefetched)
    const float* px = xlane;
    ulonglong2 X0 = *reinterpret_cast<const ulonglong2*>(px);
    ulonglong2 X1 = *reinterpret_cast<const ulonglong2*>(px + 128);
    ulonglong2 Wa = wrow[0];
    ulonglong2 Wb = wrow[1];
    ulonglong2 Wc = wrow[2];
    ulonglong2 Wd = wrow[3];

    for (int k = 0; k < kmax; ++k) {
        // ---- distance-1 prefetch (branch-free clamp) ----
        const float* pn = px + ((k + 1 < kmax) ? HW : 0);
        const ulonglong2* wn = wrow + ((k + 1 < kmax) ? (C / 2) : 0);
        ulonglong2 nX0 = *reinterpret_cast<const ulonglong2*>(pn);
        ulonglong2 nX1 = *reinterpret_cast<const ulonglong2*>(pn + 128);
        ulonglong2 nWa = wn[0];
        ulonglong2 nWb = wn[1];
        ulonglong2 nWc = wn[2];
        ulonglong2 nWd = wn[3];

        // ---- 32 packed FMAs on current operands ----
        u64 w[8] = { Wa.x, Wa.y, Wb.x, Wb.y, Wc.x, Wc.y, Wd.x, Wd.y };
#pragma unroll
        for (int j = 0; j < 8; ++j) {
            fma2(acc[j][0], w[j], X0.x);
            fma2(acc[j][1], w[j], X0.y);
            fma2(acc[j][2], w[j], X1.x);
            fma2(acc[j][3], w[j], X1.y);
        }

        X0 = nX0; X1 = nX1;
        Wa = nWa; Wb = nWb; Wc = nWc; Wd = nWd;
        px = pn; wrow = wn;
    }

    // Epilogue: bias + store (coalesced: 1 STG.128 per slice per channel)
#pragma unroll
    for (int j = 0; j < 8; ++j) {
        u64 bj = pack2(__ldg(bias + co0 + j));
        ulonglong2 v0, v1;
        v0.x = add2(acc[j][0], bj);
        v0.y = add2(acc[j][1], bj);
        v1.x = add2(acc[j][2], bj);
        v1.y = add2(acc[j][3], bj);
        float* orow = olane + (size_t)(co0 + j) * HW;
        *reinterpret_cast<ulonglong2*>(orow)       = v0;
        *reinterpret_cast<ulonglong2*>(orow + 128) = v1;
    }
}

__global__ void __launch_bounds__(THREADS, 2)
cgconv_kernel(const float* __restrict__ x,
              const float* __restrict__ bias,
              float* __restrict__ out)
{
    const int tiles_per_b = HW / PX_TILE;   // 1024
    int tile  = blockIdx.x;
    int b     = tile / tiles_per_b;
    int t_in  = tile - b * tiles_per_b;
    size_t base = (size_t)b * C * HW + (size_t)t_in * PX_TILE;

    int wid  = threadIdx.x >> 5;            // 0..7
    int lane = threadIdx.x & 31;

    const float* xlane = x   + base + (size_t)lane * 4;
    float*       olane = out + base + (size_t)lane * 4;

    // Two groups per warp: (15-wid) + (wid) -> 136 k-iters for EVERY warp
    do_group(15 - wid, xlane, bias, olane);
    do_group(wid,      xlane, bias, olane);
}

extern "C" void kernel_launch(void* const* d_in, const int* in_sizes, int n_in,
                              void* d_out, int out_size)
{
    const float* x    = (const float*)d_in[0];
    const float* w    = (const float*)d_in[1];
    const float* bias = (const float*)d_in[2];
    float* out        = (float*)d_out;

    build_w2_kernel<<<C, C>>>(w);

    int grid = BATCH * (HW / PX_TILE);  // 4096
    cgconv_kernel<<<grid, THREADS>>>(x, bias, out);
}

// round 7
// speedup vs baseline: 3.9660x; 3.9660x over previous
#include <cuda_runtime.h>
#include <cuda_bf16.h>
#include <cstdint>

// ---------------- problem constants ----------------
#define C       128
#define HW      (512 * 512)
#define BATCH   4
#define TILE_PX 128
#define TILES_PER_B (HW / TILE_PX)      // 2048
#define NT      (BATCH * TILES_PER_B)   // 8192
#define THREADS 256
#define GRID    148

// smem: 4 planes of [128 rows][136 bf16] (pitch 272B -> conflict-free ldmatrix)
#define PITCH    136
#define PITCH_B  (PITCH * 2)            // 272
#define PLANE_B  (C * PITCH_B)          // 34816
#define S_WHI    0
#define S_WLO    (S_WHI + PLANE_B)
#define S_XHI    (S_WLO + PLANE_B)
#define S_XLO    (S_XHI + PLANE_B)
#define SMEM_TOTAL (4 * PLANE_B)        // 139264

typedef unsigned long long u64;

// Masked bf16 hi/lo split of W, row-major [co][k]
__device__ __nv_bfloat16 g_Whi[C * C];
__device__ __nv_bfloat16 g_Wlo[C * C];

__global__ void build_w_kernel(const float* __restrict__ w) {
    int co = blockIdx.x;    // 0..127
    int k  = threadIdx.x;   // 0..127
    float v = ((k >> 3) <= (co >> 3)) ? w[co * C + k] : 0.0f;  // HIDDEN mask
    __nv_bfloat16 h = __float2bfloat16(v);
    float r = v - __bfloat162float(h);
    g_Whi[co * C + k] = h;
    g_Wlo[co * C + k] = __float2bfloat16(r);
}

// ---------------- helpers ----------------
__device__ __forceinline__ uint32_t smem_u32(const void* p) {
    uint32_t a;
    asm("{ .reg .u64 t; cvta.to.shared.u64 t, %1; cvt.u32.u64 %0, t; }" : "=r"(a) : "l"(p));
    return a;
}
// pack two f32 -> bf16x2 (low half = a, high half = b)
__device__ __forceinline__ uint32_t packbf2(float a, float b) {
    uint32_t r;
    asm("cvt.rn.bf16x2.f32 %0, %1, %2;" : "=r"(r) : "f"(b), "f"(a));
    return r;
}
__device__ __forceinline__ void ldsm_x4(uint32_t* r, uint32_t a) {
    asm volatile("ldmatrix.sync.aligned.m8n8.x4.shared.b16 {%0,%1,%2,%3}, [%4];"
        : "=r"(r[0]), "=r"(r[1]), "=r"(r[2]), "=r"(r[3]) : "r"(a));
}
__device__ __forceinline__ void ldsm_x4_t(uint32_t* r, uint32_t a) {
    asm volatile("ldmatrix.sync.aligned.m8n8.x4.trans.shared.b16 {%0,%1,%2,%3}, [%4];"
        : "=r"(r[0]), "=r"(r[1]), "=r"(r[2]), "=r"(r[3]) : "r"(a));
}
__device__ __forceinline__ void mma_bf16(float* d, const uint32_t* a,
                                         uint32_t b0, uint32_t b1) {
    asm volatile("mma.sync.aligned.m16n8k16.row.col.f32.bf16.bf16.f32 "
        "{%0,%1,%2,%3}, {%4,%5,%6,%7}, {%8,%9}, {%0,%1,%2,%3};"
        : "+f"(d[0]), "+f"(d[1]), "+f"(d[2]), "+f"(d[3])
        : "r"(a[0]), "r"(a[1]), "r"(a[2]), "r"(a[3]), "r"(b0), "r"(b1));
}

// ---------------- main persistent kernel ----------------
__global__ void __launch_bounds__(THREADS, 1)
cgconv_mma_kernel(const float* __restrict__ x,
                  const float* __restrict__ bias,
                  float* __restrict__ out)
{
    extern __shared__ char smem[];
    const uint32_t sb = smem_u32(smem);
    const int tid  = threadIdx.x;
    const int wid  = tid >> 5;      // 0..7 : warp owns px slice [16*wid, 16*wid+16)
    const int lane = tid & 31;

    // ---- load W hi/lo into padded smem ----
    {
        const uint4* whi = reinterpret_cast<const uint4*>(g_Whi);
        const uint4* wlo = reinterpret_cast<const uint4*>(g_Wlo);
        for (int i = tid; i < C * C / 8; i += THREADS) {   // 2048 uint4
            int row = i >> 4, c = i & 15;
            *reinterpret_cast<uint4*>(smem + S_WHI + row * PITCH_B + c * 16) = whi[i];
            *reinterpret_cast<uint4*>(smem + S_WLO + row * PITCH_B + c * 16) = wlo[i];
        }
    }

    // ---- per-thread bias registers ----
    const int qr = lane >> 2;           // accum row-within-8
    const int qc = (lane & 3) * 2;      // accum col pair
    float bias0[8], bias1[8];
#pragma unroll
    for (int m = 0; m < 8; ++m) {
        bias0[m] = __ldg(bias + m * 16 + qr);
        bias1[m] = __ldg(bias + m * 16 + 8 + qr);
    }

    // ldmatrix address components:
    // row = (lane & 15), col half selected by lane>>4
    const uint32_t arow    = (uint32_t)(lane & 15) * PITCH_B;
    const uint32_t acolsel = (uint32_t)(lane >> 4) * 16;   // 8 bf16 = 16B

    const uint32_t whi_u = sb + S_WHI + arow + acolsel;
    const uint32_t wlo_u = sb + S_WLO + arow + acolsel;
    const uint32_t xhi_u = sb + S_XHI + arow + acolsel + (uint32_t)wid * 32;
    const uint32_t xlo_u = sb + S_XLO + arow + acolsel + (uint32_t)wid * 32;

    // ---- prefetch first tile into registers ----
    // thread loads 16 row-segments: row k = wid + 8i (i=0..15), px = lane*4 .. +4
    uint4 pf[16];
    {
        int t0 = blockIdx.x;
        int b = t0 / TILES_PER_B;
        size_t xbase = (size_t)b * C * HW + (size_t)(t0 - b * TILES_PER_B) * TILE_PX;
#pragma unroll
        for (int i = 0; i < 16; ++i) {
            int k = wid + 8 * i;
            pf[i] = *reinterpret_cast<const uint4*>(x + xbase + (size_t)k * HW + lane * 4);
        }
    }

    for (int t = blockIdx.x; t < NT; t += GRID) {
        const int b   = t / TILES_PER_B;
        const int px0 = (t - b * TILES_PER_B) * TILE_PX;

        // ---- convert prefetched regs -> bf16 hi/lo smem ----
        __syncthreads();   // previous tile's readers done
#pragma unroll
        for (int i = 0; i < 16; ++i) {
            int k = wid + 8 * i;
            float fx = __uint_as_float(pf[i].x);
            float fy = __uint_as_float(pf[i].y);
            float fz = __uint_as_float(pf[i].z);
            float fw = __uint_as_float(pf[i].w);
            uint32_t h0 = packbf2(fx, fy);
            uint32_t h1 = packbf2(fz, fw);
            float r0 = fx - __uint_as_float(h0 << 16);
            float r1 = fy - __uint_as_float(h0 & 0xFFFF0000u);
            float r2 = fz - __uint_as_float(h1 << 16);
            float r3 = fw - __uint_as_float(h1 & 0xFFFF0000u);
            uint32_t l0 = packbf2(r0, r1);
            uint32_t l1 = packbf2(r2, r3);
            uint32_t off = (uint32_t)k * PITCH_B + (uint32_t)lane * 8;
            *reinterpret_cast<uint2*>(smem + S_XHI + off) = make_uint2(h0, h1);
            *reinterpret_cast<uint2*>(smem + S_XLO + off) = make_uint2(l0, l1);
        }
        __syncthreads();

        // ---- issue next tile's prefetch (latency hidden behind mma block) ----
        {
            int tn = t + GRID;
            if (tn >= NT) tn = t;
            int bn = tn / TILES_PER_B;
            size_t xb = (size_t)bn * C * HW + (size_t)(tn - bn * TILES_PER_B) * TILE_PX;
#pragma unroll
            for (int i = 0; i < 16; ++i) {
                int k = wid + 8 * i;
                pf[i] = *reinterpret_cast<const uint4*>(x + xb + (size_t)k * HW + lane * 4);
            }
        }

        // ---- triangular block GEMM: acc[m][ntile][4] ----
        float acc[8][2][4];
#pragma unroll
        for (int m = 0; m < 8; ++m)
#pragma unroll
            for (int n = 0; n < 2; ++n)
#pragma unroll
                for (int q = 0; q < 4; ++q) acc[m][n][q] = 0.0f;

#pragma unroll
        for (int kb = 0; kb < 8; ++kb) {
            uint32_t Bhi[4], Blo[4];
            ldsm_x4_t(Bhi, xhi_u + (uint32_t)kb * 16 * PITCH_B);
            ldsm_x4_t(Blo, xlo_u + (uint32_t)kb * 16 * PITCH_B);
#pragma unroll
            for (int m = 0; m < 8; ++m) {
                if (m < kb) continue;   // zero blocks (compile-time pruned)
                uint32_t Ahi[4], Alo[4];
                uint32_t aoff = (uint32_t)m * 16 * PITCH_B + (uint32_t)kb * 32;
                ldsm_x4(Ahi, whi_u + aoff);
                ldsm_x4(Alo, wlo_u + aoff);
                mma_bf16(acc[m][0], Ahi, Bhi[0], Bhi[1]);
                mma_bf16(acc[m][0], Ahi, Blo[0], Blo[1]);
                mma_bf16(acc[m][0], Alo, Bhi[0], Bhi[1]);
                mma_bf16(acc[m][1], Ahi, Bhi[2], Bhi[3]);
                mma_bf16(acc[m][1], Ahi, Blo[2], Blo[3]);
                mma_bf16(acc[m][1], Alo, Bhi[2], Bhi[3]);
            }
        }

        // ---- epilogue: bias + direct stores (32B-sector aligned float2) ----
        const size_t obase = (size_t)b * C * HW + px0 + wid * 16;
#pragma unroll
        for (int m = 0; m < 8; ++m) {
            const int ch0 = m * 16 + qr;
            const int ch1 = ch0 + 8;
            float2 v;
            v.x = acc[m][0][0] + bias0[m];
            v.y = acc[m][0][1] + bias0[m];
            *reinterpret_cast<float2*>(out + obase + (size_t)ch0 * HW + qc) = v;
            v.x = acc[m][0][2] + bias1[m];
            v.y = acc[m][0][3] + bias1[m];
            *reinterpret_cast<float2*>(out + obase + (size_t)ch1 * HW + qc) = v;
            v.x = acc[m][1][0] + bias0[m];
            v.y = acc[m][1][1] + bias0[m];
            *reinterpret_cast<float2*>(out + obase + (size_t)ch0 * HW + 8 + qc) = v;
            v.x = acc[m][1][2] + bias1[m];
            v.y = acc[m][1][3] + bias1[m];
            *reinterpret_cast<float2*>(out + obase + (size_t)ch1 * HW + 8 + qc) = v;
        }
    }
}

extern "C" void kernel_launch(void* const* d_in, const int* in_sizes, int n_in,
                              void* d_out, int out_size)
{
    const float* x    = (const float*)d_in[0];
    const float* w    = (const float*)d_in[1];
    const float* bias = (const float*)d_in[2];
    float* out        = (float*)d_out;

    cudaFuncSetAttribute(cgconv_mma_kernel,
                         cudaFuncAttributeMaxDynamicSharedMemorySize, SMEM_TOTAL);

    build_w_kernel<<<C, C>>>(w);
    cgconv_mma_kernel<<<GRID, THREADS, SMEM_TOTAL>>>(x, bias, out);
}